// round 1
// baseline (speedup 1.0000x reference)
#include <cuda_runtime.h>
#include <cuda_bf16.h>
#include <math.h>

#define C_DIM 256
#define H_DIM 16
#define HS_DIM 16
#define B_DIM 64
#define T_DIM 256
#define M_DIM (B_DIM * T_DIM)      // 16384
#define FF_DIM (4 * C_DIM)         // 1024
#define LN_EPS 1e-5f

// ---------------- scratch (static device globals; no allocation) -------------
__device__ float g_h1[M_DIM * C_DIM];
__device__ float g_q[M_DIM * C_DIM];
__device__ float g_k[M_DIM * C_DIM];
__device__ float g_v[M_DIM * C_DIM];
__device__ float g_attn[M_DIM * C_DIM];
__device__ float g_x1[M_DIM * C_DIM];
__device__ float g_h2[M_DIM * C_DIM];
__device__ float g_ffn1[M_DIM * FF_DIM];
__device__ float g_Pq[C_DIM * C_DIM];
__device__ float g_Pk[C_DIM * C_DIM];
__device__ float g_Pv[C_DIM * C_DIM];

// ---------------- LayerNorm: one block per row, 256 threads ------------------
__global__ void ln_kernel(const float* __restrict__ x,
                          const float* __restrict__ g,
                          const float* __restrict__ b,
                          float* __restrict__ out) {
    int row = blockIdx.x;
    int tid = threadIdx.x;
    const float* xr = x + (size_t)row * C_DIM;
    float v = xr[tid];
    float s = v, s2 = v * v;
    #pragma unroll
    for (int o = 16; o; o >>= 1) {
        s  += __shfl_xor_sync(0xFFFFFFFFu, s, o);
        s2 += __shfl_xor_sync(0xFFFFFFFFu, s2, o);
    }
    __shared__ float ws[8], ws2[8];
    int w = tid >> 5, l = tid & 31;
    if (l == 0) { ws[w] = s; ws2[w] = s2; }
    __syncthreads();
    if (tid < 32) {
        float t1 = (tid < 8) ? ws[tid] : 0.f;
        float t2 = (tid < 8) ? ws2[tid] : 0.f;
        #pragma unroll
        for (int o = 4; o; o >>= 1) {
            t1 += __shfl_xor_sync(0xFFFFFFFFu, t1, o);
            t2 += __shfl_xor_sync(0xFFFFFFFFu, t2, o);
        }
        if (tid == 0) { ws[0] = t1; ws2[0] = t2; }
    }
    __syncthreads();
    float mean = ws[0] * (1.f / C_DIM);
    float var  = ws2[0] * (1.f / C_DIM) - mean * mean;
    float inv  = rsqrtf(var + LN_EPS);
    out[(size_t)row * C_DIM + tid] = (v - mean) * inv * g[tid] + b[tid];
}

// ---------------- repack Wq/Wk/Wv [H,C,HS] -> [C, H*HS] ----------------------
__global__ void repack_qkv(const float* __restrict__ Wq,
                           const float* __restrict__ Wk,
                           const float* __restrict__ Wv) {
    int i = blockIdx.x * blockDim.x + threadIdx.x;  // i = c*256 + n
    if (i >= C_DIM * C_DIM) return;
    int n = i & 255;
    int c = i >> 8;
    int h = n >> 4, d = n & 15;
    int src = h * (C_DIM * HS_DIM) + c * HS_DIM + d;
    g_Pq[i] = Wq[src];
    g_Pk[i] = Wk[src];
    g_Pv[i] = Wv[src];
}

// ---------------- SGEMM: 64x64 tile, BK=16, 256 thr, 4x4 per thread ----------
// EPI: 0 = none, 2 = bias + exact GELU, 3 = bias + residual
template <int EPI>
__global__ __launch_bounds__(256) void sgemm_kernel(
    const float* __restrict__ A, const float* __restrict__ B,
    const float* __restrict__ bias, const float* __restrict__ resid,
    float* __restrict__ Cout, int M, int N, int K) {
    __shared__ float As[16][64];
    __shared__ float Bs[16][64];
    int tid = threadIdx.x;
    int tx = tid & 15, ty = tid >> 4;
    int bm = blockIdx.y * 64, bn = blockIdx.x * 64;

    int arow = tid >> 2;        // 0..63
    int acol = (tid & 3) * 4;   // 0,4,8,12
    int brow = tid >> 4;        // 0..15
    int bcol = (tid & 15) * 4;  // 0..60

    float acc[4][4] = {};

    for (int k0 = 0; k0 < K; k0 += 16) {
        float4 a = *(const float4*)&A[(size_t)(bm + arow) * K + k0 + acol];
        As[acol + 0][arow] = a.x;
        As[acol + 1][arow] = a.y;
        As[acol + 2][arow] = a.z;
        As[acol + 3][arow] = a.w;
        *(float4*)&Bs[brow][bcol] =
            *(const float4*)&B[(size_t)(k0 + brow) * N + bn + bcol];
        __syncthreads();
        #pragma unroll
        for (int kk = 0; kk < 16; kk++) {
            float4 av = *(float4*)&As[kk][ty * 4];
            float4 bv = *(float4*)&Bs[kk][tx * 4];
            float ar[4] = {av.x, av.y, av.z, av.w};
            float br[4] = {bv.x, bv.y, bv.z, bv.w};
            #pragma unroll
            for (int i = 0; i < 4; i++)
                #pragma unroll
                for (int j = 0; j < 4; j++)
                    acc[i][j] += ar[i] * br[j];
        }
        __syncthreads();
    }

    #pragma unroll
    for (int i = 0; i < 4; i++) {
        int row = bm + ty * 4 + i;
        #pragma unroll
        for (int j = 0; j < 4; j++) {
            int col = bn + tx * 4 + j;
            float v = acc[i][j];
            if (EPI >= 2) v += bias[col];
            if (EPI == 2) v = 0.5f * v * (1.0f + erff(v * 0.70710678118654752f));
            if (EPI == 3) v += resid[(size_t)row * N + col];
            Cout[(size_t)row * N + col] = v;
        }
    }
}

// ---------------- attention: one block per (b,h), one thread per query row ---
__global__ __launch_bounds__(256) void attn_kernel(
    const float* __restrict__ q, const float* __restrict__ k,
    const float* __restrict__ v, float* __restrict__ out) {
    int h = blockIdx.x;  // 0..15
    int b = blockIdx.y;  // 0..63
    __shared__ float Ks[T_DIM][HS_DIM];
    __shared__ float Vs[T_DIM][HS_DIM];
    int tid = threadIdx.x;  // 0..255 = query row t

    const float* kb = k + ((size_t)b * T_DIM) * C_DIM + h * HS_DIM;
    const float* vb = v + ((size_t)b * T_DIM) * C_DIM + h * HS_DIM;
    #pragma unroll
    for (int d = 0; d < HS_DIM; d += 4) {
        *(float4*)&Ks[tid][d] = *(const float4*)&kb[(size_t)tid * C_DIM + d];
        *(float4*)&Vs[tid][d] = *(const float4*)&vb[(size_t)tid * C_DIM + d];
    }
    __syncthreads();

    int t = tid;
    float qr[HS_DIM];
    const float* qb = q + ((size_t)(b * T_DIM + t)) * C_DIM + h * HS_DIM;
    #pragma unroll
    for (int d = 0; d < HS_DIM; d += 4) {
        float4 qv = *(const float4*)&qb[d];
        qr[d] = qv.x; qr[d + 1] = qv.y; qr[d + 2] = qv.z; qr[d + 3] = qv.w;
    }

    const float scale = 0.0625f;  // 1/sqrt(C)=1/16 (NOTE: C, not HS, per reference)
    float m = -1e30f, l = 0.f;
    float acc[HS_DIM];
    #pragma unroll
    for (int d = 0; d < HS_DIM; d++) acc[d] = 0.f;

    for (int j = 0; j <= t; j++) {
        float s = 0.f;
        #pragma unroll
        for (int d = 0; d < HS_DIM; d++) s += qr[d] * Ks[j][d];
        s *= scale;
        if (s > m) {
            float corr = expf(m - s);
            l *= corr;
            #pragma unroll
            for (int d = 0; d < HS_DIM; d++) acc[d] *= corr;
            m = s;
        }
        float p = expf(s - m);
        l += p;
        #pragma unroll
        for (int d = 0; d < HS_DIM; d++) acc[d] += p * Vs[j][d];
    }
    float inv = 1.f / l;
    float* ob = out + ((size_t)(b * T_DIM + t)) * C_DIM + h * HS_DIM;
    #pragma unroll
    for (int d = 0; d < HS_DIM; d++) ob[d] = acc[d] * inv;
}

// ---------------- launch ------------------------------------------------------
extern "C" void kernel_launch(void* const* d_in, const int* in_sizes, int n_in,
                              void* d_out, int out_size) {
    const float* x  = (const float*)d_in[0];
    const float* Wq = (const float*)d_in[1];
    const float* Wk = (const float*)d_in[2];
    const float* Wv = (const float*)d_in[3];
    const float* Wp = (const float*)d_in[4];
    const float* bp = (const float*)d_in[5];
    const float* W1 = (const float*)d_in[6];
    const float* b1 = (const float*)d_in[7];
    const float* W2 = (const float*)d_in[8];
    const float* b2 = (const float*)d_in[9];
    const float* g1  = (const float*)d_in[10];
    const float* be1 = (const float*)d_in[11];
    const float* g2  = (const float*)d_in[12];
    const float* be2 = (const float*)d_in[13];
    float* out = (float*)d_out;

    float *h1, *q, *k, *v, *attn, *x1, *h2, *ffn1, *Pq, *Pk, *Pv;
    cudaGetSymbolAddress((void**)&h1,  g_h1);
    cudaGetSymbolAddress((void**)&q,   g_q);
    cudaGetSymbolAddress((void**)&k,   g_k);
    cudaGetSymbolAddress((void**)&v,   g_v);
    cudaGetSymbolAddress((void**)&attn,g_attn);
    cudaGetSymbolAddress((void**)&x1,  g_x1);
    cudaGetSymbolAddress((void**)&h2,  g_h2);
    cudaGetSymbolAddress((void**)&ffn1,g_ffn1);
    cudaGetSymbolAddress((void**)&Pq,  g_Pq);
    cudaGetSymbolAddress((void**)&Pk,  g_Pk);
    cudaGetSymbolAddress((void**)&Pv,  g_Pv);

    // 1. LN1
    ln_kernel<<<M_DIM, 256>>>(x, g1, be1, h1);
    // 2. repack per-head weights to [C, C]
    repack_qkv<<<(C_DIM * C_DIM + 255) / 256, 256>>>(Wq, Wk, Wv);
    // 3. QKV projections  [M,C] @ [C,C]
    dim3 gCC(C_DIM / 64, M_DIM / 64);
    sgemm_kernel<0><<<gCC, 256>>>(h1, Pq, nullptr, nullptr, q, M_DIM, C_DIM, C_DIM);
    sgemm_kernel<0><<<gCC, 256>>>(h1, Pk, nullptr, nullptr, k, M_DIM, C_DIM, C_DIM);
    sgemm_kernel<0><<<gCC, 256>>>(h1, Pv, nullptr, nullptr, v, M_DIM, C_DIM, C_DIM);
    // 4. attention
    attn_kernel<<<dim3(H_DIM, B_DIM), 256>>>(q, k, v, attn);
    // 5. proj + bias + residual(x)
    sgemm_kernel<3><<<gCC, 256>>>(attn, Wp, bp, x, x1, M_DIM, C_DIM, C_DIM);
    // 6. LN2
    ln_kernel<<<M_DIM, 256>>>(x1, g2, be2, h2);
    // 7. FFN up + GELU   [M,C] @ [C,4C]
    dim3 gCF(FF_DIM / 64, M_DIM / 64);
    sgemm_kernel<2><<<gCF, 256>>>(h2, W1, b1, nullptr, ffn1, M_DIM, FF_DIM, C_DIM);
    // 8. FFN down + bias + residual(x1)  [M,4C] @ [4C,C]
    sgemm_kernel<3><<<gCC, 256>>>(ffn1, W2, b2, x1, out, M_DIM, C_DIM, FF_DIM);
}

// round 3
// speedup vs baseline: 2.4704x; 2.4704x over previous
#include <cuda_runtime.h>
#include <cuda_bf16.h>
#include <math.h>
#include <stdint.h>

#define C_DIM 256
#define H_DIM 16
#define HS_DIM 16
#define B_DIM 64
#define T_DIM 256
#define M_DIM 16384
#define FF_DIM 1024
#define QKV_N 768
#define LN_EPS 1e-5f

// ---------------- scratch ----------------------------------------------------
__device__ float g_h1[M_DIM * C_DIM];
__device__ float g_qkv[M_DIM * QKV_N];
__device__ float g_attn[M_DIM * C_DIM];
__device__ float g_x1[M_DIM * C_DIM];
__device__ float g_h2[M_DIM * C_DIM];
__device__ float g_ffn1[M_DIM * FF_DIM];
__device__ float g_Wqkv[QKV_N * C_DIM];   // [N,K] K-major
__device__ float g_WpT[C_DIM * C_DIM];
__device__ float g_W1T[FF_DIM * C_DIM];
__device__ float g_W2T[C_DIM * FF_DIM];

// ---------------- helpers ----------------------------------------------------
__device__ __forceinline__ uint32_t smem_u32(const void* p) {
    uint32_t a;
    asm("{ .reg .u64 t; cvta.to.shared.u64 t, %1; cvt.u32.u64 %0, t; }" : "=r"(a) : "l"(p));
    return a;
}
static __device__ __forceinline__ void cp_async16(uint32_t dst, const void* src) {
    asm volatile("cp.async.cg.shared.global [%0], [%1], 16;" :: "r"(dst), "l"(src) : "memory");
}
#define CP_COMMIT() asm volatile("cp.async.commit_group;" ::: "memory")
template <int N> __device__ __forceinline__ void cp_wait() {
    asm volatile("cp.async.wait_group %0;" :: "n"(N) : "memory");
}

// mma.sync m16n8k8 tf32 (inputs are raw fp32 bits; HW truncates to tf32)
__device__ __forceinline__ void mma_tf32(float* c, uint32_t a0, uint32_t a1,
                                         uint32_t a2, uint32_t a3,
                                         uint32_t b0, uint32_t b1) {
    asm volatile(
        "mma.sync.aligned.m16n8k8.row.col.f32.tf32.tf32.f32 "
        "{%0,%1,%2,%3}, {%4,%5,%6,%7}, {%8,%9}, {%0,%1,%2,%3};"
        : "+f"(c[0]), "+f"(c[1]), "+f"(c[2]), "+f"(c[3])
        : "r"(a0), "r"(a1), "r"(a2), "r"(a3), "r"(b0), "r"(b1));
}

// ---------------- LayerNorm --------------------------------------------------
__global__ void ln_kernel(const float* __restrict__ x, const float* __restrict__ g,
                          const float* __restrict__ b, float* __restrict__ out) {
    int row = blockIdx.x, tid = threadIdx.x;
    float v = x[(size_t)row * C_DIM + tid];
    float s = v, s2 = v * v;
    #pragma unroll
    for (int o = 16; o; o >>= 1) {
        s += __shfl_xor_sync(0xFFFFFFFFu, s, o);
        s2 += __shfl_xor_sync(0xFFFFFFFFu, s2, o);
    }
    __shared__ float ws[8], ws2[8];
    int w = tid >> 5, l = tid & 31;
    if (l == 0) { ws[w] = s; ws2[w] = s2; }
    __syncthreads();
    if (tid < 32) {
        float t1 = (tid < 8) ? ws[tid] : 0.f;
        float t2 = (tid < 8) ? ws2[tid] : 0.f;
        #pragma unroll
        for (int o = 4; o; o >>= 1) {
            t1 += __shfl_xor_sync(0xFFFFFFFFu, t1, o);
            t2 += __shfl_xor_sync(0xFFFFFFFFu, t2, o);
        }
        if (tid == 0) { ws[0] = t1; ws2[0] = t2; }
    }
    __syncthreads();
    float mean = ws[0] * (1.f / C_DIM);
    float var = ws2[0] * (1.f / C_DIM) - mean * mean;
    out[(size_t)row * C_DIM + tid] = (v - mean) * rsqrtf(var + LN_EPS) * g[tid] + b[tid];
}

// ---------------- weight repack to [N,K] K-major -----------------------------
__global__ void repack_qkv(const float* __restrict__ Wq, const float* __restrict__ Wk,
                           const float* __restrict__ Wv) {
    int i = blockIdx.x * blockDim.x + threadIdx.x;
    if (i >= QKV_N * C_DIM) return;
    int n = i >> 8, k = i & 255;
    int sel = n >> 8, nn = n & 255;
    int h = nn >> 4, d = nn & 15;
    int src = h * (C_DIM * HS_DIM) + k * HS_DIM + d;
    const float* W = (sel == 0) ? Wq : (sel == 1) ? Wk : Wv;
    g_Wqkv[i] = W[src];
}
__global__ void repack_rest(const float* __restrict__ Wp, const float* __restrict__ W1,
                            const float* __restrict__ W2) {
    int i = blockIdx.x * blockDim.x + threadIdx.x;
    if (i < C_DIM * C_DIM) g_WpT[i] = Wp[(i & 255) * C_DIM + (i >> 8)];
    if (i < FF_DIM * C_DIM) g_W1T[i] = W1[(i & 255) * FF_DIM + (i >> 8)];
    if (i < C_DIM * FF_DIM) g_W2T[i] = W2[(i & 1023) * C_DIM + (i >> 10)];
}

// ---------------- tf32 mma.sync GEMM -----------------------------------------
// CTA tile 128x128, BK=32, 256 threads = 8 warps (2 M x 4 N), warp tile 64x32.
// smem tiles [128][36] fp32 (pad 4 -> conflict-free frag reads), cp.async 2-stage.
#define BK 32
#define TILE_F  (128 * 36)          // floats per tile
#define TILE_B  (TILE_F * 4)        // 18432 bytes
#define STAGE_B (2 * TILE_B)        // A + B per stage
#define GEMM_SMEM (2 * STAGE_B)     // 73728 bytes

__device__ __forceinline__ void load_tile(uint32_t sdst, const float* __restrict__ gp,
                                          int ld, int row0, int kc, int tid) {
    #pragma unroll
    for (int i = 0; i < 4; i++) {
        int f = i * 256 + tid;       // float4 index over 128x32
        int row = f >> 3;
        int c4 = (f & 7) * 4;
        cp_async16(sdst + (uint32_t)(row * 144 + c4 * 4),
                   gp + (size_t)(row0 + row) * ld + kc + c4);
    }
}

// EPI: 0 none, 2 bias+GELU, 3 bias+residual
template <int EPI>
__global__ __launch_bounds__(256, 2) void mma_gemm(
    const float* __restrict__ A, const float* __restrict__ Bw,
    const float* __restrict__ bias, const float* __restrict__ resid,
    float* __restrict__ out, int M, int N, int K) {
    extern __shared__ float smem[];
    uint32_t sb = smem_u32(smem);
    int tid = threadIdx.x, wid = tid >> 5, lane = tid & 31;
    int g = lane >> 2, t = lane & 3;
    int warpM = wid & 1, warpN = wid >> 1;          // 2 x 4 warp grid
    int mbase = warpM * 64, nbase = warpN * 32;
    int bm = blockIdx.y * 128, bn = blockIdx.x * 128;
    int nc = K >> 5;

    float acc[4][4][4];
    #pragma unroll
    for (int i = 0; i < 4; i++)
        #pragma unroll
        for (int j = 0; j < 4; j++)
            #pragma unroll
            for (int e = 0; e < 4; e++) acc[i][j][e] = 0.f;

    // prologue: chunk 0 -> stage 0
    load_tile(sb, A, K, bm, 0, tid);
    load_tile(sb + TILE_B, Bw, K, bn, 0, tid);
    CP_COMMIT();

    for (int c = 0; c < nc; c++) {
        if (c + 1 < nc) {
            uint32_t st = sb + ((c + 1) & 1) * STAGE_B;
            load_tile(st, A, K, bm, (c + 1) << 5, tid);
            load_tile(st + TILE_B, Bw, K, bn, (c + 1) << 5, tid);
            CP_COMMIT();
            cp_wait<1>();
        } else {
            cp_wait<0>();
        }
        __syncthreads();

        const float* sA = smem + (c & 1) * (STAGE_B / 4);
        const float* sB = sA + TILE_F;
        #pragma unroll
        for (int kk = 0; kk < 4; kk++) {
            int k0 = kk * 8 + t;
            uint32_t af[4][4];
            #pragma unroll
            for (int mt = 0; mt < 4; mt++) {
                int r0 = mbase + mt * 16 + g;
                af[mt][0] = __float_as_uint(sA[r0 * 36 + k0]);
                af[mt][1] = __float_as_uint(sA[(r0 + 8) * 36 + k0]);
                af[mt][2] = __float_as_uint(sA[r0 * 36 + k0 + 4]);
                af[mt][3] = __float_as_uint(sA[(r0 + 8) * 36 + k0 + 4]);
            }
            uint32_t bf[4][2];
            #pragma unroll
            for (int nt = 0; nt < 4; nt++) {
                int rn = nbase + nt * 8 + g;
                bf[nt][0] = __float_as_uint(sB[rn * 36 + k0]);
                bf[nt][1] = __float_as_uint(sB[rn * 36 + k0 + 4]);
            }
            #pragma unroll
            for (int mt = 0; mt < 4; mt++)
                #pragma unroll
                for (int nt = 0; nt < 4; nt++)
                    mma_tf32(acc[mt][nt], af[mt][0], af[mt][1], af[mt][2], af[mt][3],
                             bf[nt][0], bf[nt][1]);
        }
        __syncthreads();
    }

    // epilogue: acc[mt][nt] maps (row = bm+mbase+mt*16+g (+8), col = bn+nbase+nt*8+2t)
    #pragma unroll
    for (int mt = 0; mt < 4; mt++) {
        int row = bm + mbase + mt * 16 + g;
        #pragma unroll
        for (int nt = 0; nt < 4; nt++) {
            int col = bn + nbase + nt * 8 + 2 * t;
            float2 v0 = make_float2(acc[mt][nt][0], acc[mt][nt][1]);
            float2 v1 = make_float2(acc[mt][nt][2], acc[mt][nt][3]);
            if (EPI >= 2) {
                float2 bv = *(const float2*)&bias[col];
                v0.x += bv.x; v0.y += bv.y; v1.x += bv.x; v1.y += bv.y;
            }
            if (EPI == 2) {
                v0.x = 0.5f * v0.x * (1.f + erff(v0.x * 0.70710678118654752f));
                v0.y = 0.5f * v0.y * (1.f + erff(v0.y * 0.70710678118654752f));
                v1.x = 0.5f * v1.x * (1.f + erff(v1.x * 0.70710678118654752f));
                v1.y = 0.5f * v1.y * (1.f + erff(v1.y * 0.70710678118654752f));
            }
            if (EPI == 3) {
                float2 r0 = *(const float2*)&resid[(size_t)row * N + col];
                float2 r1 = *(const float2*)&resid[(size_t)(row + 8) * N + col];
                v0.x += r0.x; v0.y += r0.y; v1.x += r1.x; v1.y += r1.y;
            }
            *(float2*)&out[(size_t)row * N + col] = v0;
            *(float2*)&out[(size_t)(row + 8) * N + col] = v1;
        }
    }
}

// ---------------- attention --------------------------------------------------
__global__ __launch_bounds__(256) void attn_kernel(const float* __restrict__ qkv,
                                                   float* __restrict__ out) {
    int h = blockIdx.x, b = blockIdx.y;
    __shared__ float Ks[T_DIM][HS_DIM];
    __shared__ float Vs[T_DIM][HS_DIM];
    int tid = threadIdx.x;

    const float* base = qkv + (size_t)(b * T_DIM) * QKV_N;
    #pragma unroll
    for (int d = 0; d < HS_DIM; d += 4) {
        *(float4*)&Ks[tid][d] = *(const float4*)&base[(size_t)tid * QKV_N + 256 + h * 16 + d];
        *(float4*)&Vs[tid][d] = *(const float4*)&base[(size_t)tid * QKV_N + 512 + h * 16 + d];
    }
    __syncthreads();

    int t = tid;
    float qr[HS_DIM];
    const float* qb = base + (size_t)t * QKV_N + h * 16;
    #pragma unroll
    for (int d = 0; d < HS_DIM; d += 4) {
        float4 qv = *(const float4*)&qb[d];
        qr[d] = qv.x; qr[d + 1] = qv.y; qr[d + 2] = qv.z; qr[d + 3] = qv.w;
    }
    const float scale = 0.0625f;  // 1/sqrt(C), per reference
    float m = -1e30f, l = 0.f, acc[HS_DIM];
    #pragma unroll
    for (int d = 0; d < HS_DIM; d++) acc[d] = 0.f;
    for (int j = 0; j <= t; j++) {
        float s = 0.f;
        #pragma unroll
        for (int d = 0; d < HS_DIM; d++) s += qr[d] * Ks[j][d];
        s *= scale;
        if (s > m) {
            float corr = __expf(m - s);
            l *= corr;
            #pragma unroll
            for (int d = 0; d < HS_DIM; d++) acc[d] *= corr;
            m = s;
        }
        float p = __expf(s - m);
        l += p;
        #pragma unroll
        for (int d = 0; d < HS_DIM; d++) acc[d] += p * Vs[j][d];
    }
    float inv = 1.f / l;
    float* ob = out + (size_t)(b * T_DIM + t) * C_DIM + h * 16;
    #pragma unroll
    for (int d = 0; d < HS_DIM; d++) ob[d] = acc[d] * inv;
}

// ---------------- launch -----------------------------------------------------
extern "C" void kernel_launch(void* const* d_in, const int* in_sizes, int n_in,
                              void* d_out, int out_size) {
    const float* x = (const float*)d_in[0];
    const float* Wq = (const float*)d_in[1];
    const float* Wk = (const float*)d_in[2];
    const float* Wv = (const float*)d_in[3];
    const float* Wp = (const float*)d_in[4];
    const float* bp = (const float*)d_in[5];
    const float* W1 = (const float*)d_in[6];
    const float* b1 = (const float*)d_in[7];
    const float* W2 = (const float*)d_in[8];
    const float* b2 = (const float*)d_in[9];
    const float* g1 = (const float*)d_in[10];
    const float* be1 = (const float*)d_in[11];
    const float* g2 = (const float*)d_in[12];
    const float* be2 = (const float*)d_in[13];
    float* out = (float*)d_out;

    float *h1, *qkv, *attn, *x1, *h2, *ffn1, *Wqkv, *WpT, *W1T, *W2T;
    cudaGetSymbolAddress((void**)&h1, g_h1);
    cudaGetSymbolAddress((void**)&qkv, g_qkv);
    cudaGetSymbolAddress((void**)&attn, g_attn);
    cudaGetSymbolAddress((void**)&x1, g_x1);
    cudaGetSymbolAddress((void**)&h2, g_h2);
    cudaGetSymbolAddress((void**)&ffn1, g_ffn1);
    cudaGetSymbolAddress((void**)&Wqkv, g_Wqkv);
    cudaGetSymbolAddress((void**)&WpT, g_WpT);
    cudaGetSymbolAddress((void**)&W1T, g_W1T);
    cudaGetSymbolAddress((void**)&W2T, g_W2T);

    cudaFuncSetAttribute(mma_gemm<0>, cudaFuncAttributeMaxDynamicSharedMemorySize, GEMM_SMEM);
    cudaFuncSetAttribute(mma_gemm<2>, cudaFuncAttributeMaxDynamicSharedMemorySize, GEMM_SMEM);
    cudaFuncSetAttribute(mma_gemm<3>, cudaFuncAttributeMaxDynamicSharedMemorySize, GEMM_SMEM);

    ln_kernel<<<M_DIM, 256>>>(x, g1, be1, h1);
    repack_qkv<<<(QKV_N * C_DIM + 255) / 256, 256>>>(Wq, Wk, Wv);
    repack_rest<<<(FF_DIM * C_DIM + 255) / 256, 256>>>(Wp, W1, W2);

    // QKV: [M,256] @ [256,768]
    mma_gemm<0><<<dim3(QKV_N / 128, M_DIM / 128), 256, GEMM_SMEM>>>(
        h1, Wqkv, nullptr, nullptr, qkv, M_DIM, QKV_N, C_DIM);
    attn_kernel<<<dim3(H_DIM, B_DIM), 256>>>(qkv, attn);
    // proj + bias + residual(x)
    mma_gemm<3><<<dim3(C_DIM / 128, M_DIM / 128), 256, GEMM_SMEM>>>(
        attn, WpT, bp, x, x1, M_DIM, C_DIM, C_DIM);
    ln_kernel<<<M_DIM, 256>>>(x1, g2, be2, h2);
    // FFN up + GELU
    mma_gemm<2><<<dim3(FF_DIM / 128, M_DIM / 128), 256, GEMM_SMEM>>>(
        h2, W1T, b1, nullptr, ffn1, M_DIM, FF_DIM, C_DIM);
    // FFN down + bias + residual(x1)
    mma_gemm<3><<<dim3(C_DIM / 128, M_DIM / 128), 256, GEMM_SMEM>>>(
        ffn1, W2T, b2, x1, out, M_DIM, C_DIM, FF_DIM);
}